// round 1
// baseline (speedup 1.0000x reference)
#include <cuda_runtime.h>

// FixedChannelDP: y[p, n] = sum_{k=0}^{512} h[k] * x[p, n-k]  (full conv, zero-padded)
// Output layout: [2, NOUT, 2] f32 == float2 (re, im) per sample.

#define NTAPS   513
#define HALO    512          // NTAPS - 1
#define TILE    2048         // outputs per CTA
#define THREADS 256
#define PT      8            // outputs per thread
#define XTILE   (TILE + HALO)  // 2560 complex samples staged in smem

typedef unsigned long long u64;

__device__ __forceinline__ u64 pack2(float lo, float hi) {
    u64 r;
    asm("mov.b64 %0, {%1, %2};" : "=l"(r) : "f"(lo), "f"(hi));
    return r;
}

__device__ __forceinline__ u64 fma2(u64 a, u64 b, u64 c) {
    u64 d;
    asm("fma.rn.f32x2 %0, %1, %2, %3;" : "=l"(d) : "l"(a), "l"(b), "l"(c));
    return d;
}

__device__ __forceinline__ float2 unpack2(u64 v) {
    float lo, hi;
    asm("mov.b64 {%0, %1}, %2;" : "=f"(lo), "=f"(hi) : "l"(v));
    return make_float2(lo, hi);
}

__global__ void __launch_bounds__(THREADS, 2)
conv_dp_kernel(const float* __restrict__ txr, const float* __restrict__ txi,
               const float* __restrict__ hre, const float* __restrict__ him,
               float2* __restrict__ out, int N, int NOUT)
{
    __shared__ float2 sx[XTILE];   // (xr, xi) zero-padded tile
    __shared__ float4 sh[NTAPS];   // (hr, hr, -hi, hi) per tap

    const int pol = blockIdx.y;
    const int tileStart = blockIdx.x * TILE;
    const float* __restrict__ xr = txr + (size_t)pol * N;
    const float* __restrict__ xi = txi + (size_t)pol * N;

    // Stage x tile [tileStart-512, tileStart+2047] with zero padding.
    for (int i = threadIdx.x; i < XTILE; i += THREADS) {
        int g = tileStart - HALO + i;
        float a = 0.0f, b = 0.0f;
        if ((unsigned)g < (unsigned)N) { a = xr[g]; b = xi[g]; }
        sx[i] = make_float2(a, b);
    }
    // Stage packed taps.
    for (int k = threadIdx.x; k < NTAPS; k += THREADS) {
        float r = hre[k], m = him[k];
        sh[k] = make_float4(r, r, -m, m);
    }
    __syncthreads();

    const int base = threadIdx.x * PT;

    u64 acc[PT];
    u64 w[16], ws[16];   // packed (xr,xi) and swapped (xi,xr) register windows
#pragma unroll
    for (int j = 0; j < PT; j++) acc[j] = pack2(0.0f, 0.0f);

    // Preload window: w[u] = sx[base + u]  (corresponds to tap k=512 positions)
#pragma unroll
    for (int u = 0; u < 8; u++) {
        float2 v = sx[base + u];
        w[u]  = pack2(v.x, v.y);
        ws[u] = pack2(v.y, v.x);
    }

    // Taps k = 512 .. 1 in 64 chunks of 8 (kk = 512-k = 8c + t).
    // For output j and tap step kk, x lives at sx[base + 8c + (j + t)], j+t in [0,14].
#pragma unroll 1
    for (int c = 0; c < 64; c++) {
#pragma unroll
        for (int u = 0; u < 8; u++) {
            float2 v = sx[base + 8 * c + 8 + u];
            w[8 + u]  = pack2(v.x, v.y);
            ws[8 + u] = pack2(v.y, v.x);
        }
#pragma unroll
        for (int t = 0; t < 8; t++) {
            float4 h4 = sh[512 - 8 * c - t];
            u64 hrr = pack2(h4.x, h4.y);   // ( hr, hr)
            u64 hmi = pack2(h4.z, h4.w);   // (-hi, hi)
#pragma unroll
            for (int j = 0; j < PT; j++) {
                acc[j] = fma2(hrr, w[j + t],  acc[j]);  // (+hr*xr, +hr*xi)
                acc[j] = fma2(hmi, ws[j + t], acc[j]);  // (-hi*xi, +hi*xr)
            }
        }
#pragma unroll
        for (int u = 0; u < 8; u++) { w[u] = w[8 + u]; ws[u] = ws[8 + u]; }
    }

    // Remainder tap k = 0 (kk = 512): x index = base + 512 + j = rotated w[j].
    {
        float4 h4 = sh[0];
        u64 hrr = pack2(h4.x, h4.y);
        u64 hmi = pack2(h4.z, h4.w);
#pragma unroll
        for (int j = 0; j < PT; j++) {
            acc[j] = fma2(hrr, w[j],  acc[j]);
            acc[j] = fma2(hmi, ws[j], acc[j]);
        }
    }

    // Store 8 consecutive complex outputs. NOUT % 8 == 0, so a thread is
    // either fully in-range or fully out.
    const int n0 = tileStart + base;
    if (n0 + PT <= NOUT) {
        float2* o = out + (size_t)pol * NOUT + n0;
#pragma unroll
        for (int j = 0; j < PT; j++) o[j] = unpack2(acc[j]);
    }
}

extern "C" void kernel_launch(void* const* d_in, const int* in_sizes, int n_in,
                              void* d_out, int out_size)
{
    const float* txr = (const float*)d_in[0];  // [2, N]
    const float* txi = (const float*)d_in[1];  // [2, N]
    const float* hre = (const float*)d_in[2];  // [L]
    const float* him = (const float*)d_in[3];  // [L]

    const int N    = in_sizes[0] / 2;
    const int L    = in_sizes[2];
    const int NOUT = N + L - 1;

    const int tiles = (NOUT + TILE - 1) / TILE;
    dim3 grid(tiles, 2);
    conv_dp_kernel<<<grid, THREADS>>>(txr, txi, hre, him, (float2*)d_out, N, NOUT);
}

// round 4
// speedup vs baseline: 1.5346x; 1.5346x over previous
#include <cuda_runtime.h>

// FixedChannelDP: y[p, n] = sum_{k=0}^{512} h[k] * x[p, n-k]  (full conv, zero-padded)
// Output layout: [2, NOUT, 2] f32 == float2 (re, im) per sample.
//
// R2 change (resubmitted; broker timeouts in R2/R3): bank-conflict-free smem
// layout for the x tile. phys(i) = i + (i>>3): per-lane 64-byte-strided window
// loads map to 16 distinct even/odd bank pairs per LDS.64 half-warp phase.

#define NTAPS   513
#define HALO    512          // NTAPS - 1
#define TILE    2048         // outputs per CTA
#define THREADS 256
#define PT      8            // outputs per thread
#define XTILE   (TILE + HALO)          // 2560 logical complex samples
#define XPHYS   (XTILE + XTILE / 8)    // 2880 with padding

#define SIDX(i) ((i) + ((i) >> 3))

typedef unsigned long long u64;

__device__ __forceinline__ u64 pack2(float lo, float hi) {
    u64 r;
    asm("mov.b64 %0, {%1, %2};" : "=l"(r) : "f"(lo), "f"(hi));
    return r;
}

__device__ __forceinline__ u64 fma2(u64 a, u64 b, u64 c) {
    u64 d;
    asm("fma.rn.f32x2 %0, %1, %2, %3;" : "=l"(d) : "l"(a), "l"(b), "l"(c));
    return d;
}

__device__ __forceinline__ float2 unpack2(u64 v) {
    float lo, hi;
    asm("mov.b64 {%0, %1}, %2;" : "=f"(lo), "=f"(hi) : "l"(v));
    return make_float2(lo, hi);
}

__global__ void __launch_bounds__(THREADS, 2)
conv_dp_kernel(const float* __restrict__ txr, const float* __restrict__ txi,
               const float* __restrict__ hre, const float* __restrict__ him,
               float2* __restrict__ out, int N, int NOUT)
{
    __shared__ float2 sx[XPHYS];   // (xr, xi) zero-padded tile, bank-padded
    __shared__ float4 sh[NTAPS];   // (hr, hr, -hi, hi) per tap

    const int pol = blockIdx.y;
    const int tileStart = blockIdx.x * TILE;
    const float* __restrict__ xr = txr + (size_t)pol * N;
    const float* __restrict__ xi = txi + (size_t)pol * N;

    // Stage x tile [tileStart-512, tileStart+2047] with zero padding.
    for (int i = threadIdx.x; i < XTILE; i += THREADS) {
        int g = tileStart - HALO + i;
        float a = 0.0f, b = 0.0f;
        if ((unsigned)g < (unsigned)N) { a = xr[g]; b = xi[g]; }
        sx[SIDX(i)] = make_float2(a, b);
    }
    // Stage packed taps.
    for (int k = threadIdx.x; k < NTAPS; k += THREADS) {
        float r = hre[k], m = him[k];
        sh[k] = make_float4(r, r, -m, m);
    }
    __syncthreads();

    const int base = threadIdx.x * PT;

    u64 acc[PT];
    u64 w[16], ws[16];   // packed (xr,xi) and swapped (xi,xr) register windows
#pragma unroll
    for (int j = 0; j < PT; j++) acc[j] = pack2(0.0f, 0.0f);

    // Preload window: w[u] = sx[base + u]  (corresponds to tap k=512 positions)
#pragma unroll
    for (int u = 0; u < 8; u++) {
        float2 v = sx[SIDX(base + u)];
        w[u]  = pack2(v.x, v.y);
        ws[u] = pack2(v.y, v.x);
    }

    // Taps k = 512 .. 1 in 64 chunks of 8 (kk = 512-k = 8c + t).
    // For output j and tap step kk, x lives at sx[base + 8c + (j + t)], j+t in [0,14].
#pragma unroll 1
    for (int c = 0; c < 64; c++) {
#pragma unroll
        for (int u = 0; u < 8; u++) {
            float2 v = sx[SIDX(base + 8 * c + 8 + u)];
            w[8 + u]  = pack2(v.x, v.y);
            ws[8 + u] = pack2(v.y, v.x);
        }
#pragma unroll
        for (int t = 0; t < 8; t++) {
            float4 h4 = sh[512 - 8 * c - t];
            u64 hrr = pack2(h4.x, h4.y);   // ( hr, hr)
            u64 hmi = pack2(h4.z, h4.w);   // (-hi, hi)
#pragma unroll
            for (int j = 0; j < PT; j++) {
                acc[j] = fma2(hrr, w[j + t],  acc[j]);  // (+hr*xr, +hr*xi)
                acc[j] = fma2(hmi, ws[j + t], acc[j]);  // (-hi*xi, +hi*xr)
            }
        }
#pragma unroll
        for (int u = 0; u < 8; u++) { w[u] = w[8 + u]; ws[u] = ws[8 + u]; }
    }

    // Remainder tap k = 0 (kk = 512): x index = base + 512 + j = rotated w[j].
    {
        float4 h4 = sh[0];
        u64 hrr = pack2(h4.x, h4.y);
        u64 hmi = pack2(h4.z, h4.w);
#pragma unroll
        for (int j = 0; j < PT; j++) {
            acc[j] = fma2(hrr, w[j],  acc[j]);
            acc[j] = fma2(hmi, ws[j], acc[j]);
        }
    }

    // Store 8 consecutive complex outputs. A thread is fully in-range or fully out.
    const int n0 = tileStart + base;
    if (n0 + PT <= NOUT) {
        float2* o = out + (size_t)pol * NOUT + n0;
#pragma unroll
        for (int j = 0; j < PT; j++) o[j] = unpack2(acc[j]);
    }
}

extern "C" void kernel_launch(void* const* d_in, const int* in_sizes, int n_in,
                              void* d_out, int out_size)
{
    const float* txr = (const float*)d_in[0];  // [2, N]
    const float* txi = (const float*)d_in[1];  // [2, N]
    const float* hre = (const float*)d_in[2];  // [L]
    const float* him = (const float*)d_in[3];  // [L]

    const int N    = in_sizes[0] / 2;
    const int L    = in_sizes[2];
    const int NOUT = N + L - 1;

    const int tiles = (NOUT + TILE - 1) / TILE;
    dim3 grid(tiles, 2);
    conv_dp_kernel<<<grid, THREADS>>>(txr, txi, hre, him, (float2*)d_out, N, NOUT);
}

// round 5
// speedup vs baseline: 1.6046x; 1.0456x over previous
#include <cuda_runtime.h>

// FixedChannelDP: y[p, n] = sum_{k=0}^{512} h[k] * x[p, n-k]  (full conv, zero-padded)
// Output layout: [2, NOUT, 2] f32 == float2 (re, im) per sample.
//
// R5 changes:
//  1. No swapped window: accA += (hr,hr)*(xr,xi), accB += (hi,hi)*(xr,xi);
//     combine y = (accA.lo - accB.hi, accA.hi + accB.lo) once at the end.
//  2. Ping-pong 16-slot circular window (chunk loop unrolled x2) -> zero
//     rotation/swap MOVs in the hot loop.
//  3. __launch_bounds__(256, 3): 6 warps/SMSP for latency cover.
// Keeps R4's bank-conflict-free smem padding SIDX(i) = i + (i>>3).

#define NTAPS   513
#define HALO    512
#define TILE    2048
#define THREADS 256
#define PT      8
#define XTILE   (TILE + HALO)          // 2560 logical complex samples
#define XPHYS   (XTILE + XTILE / 8)    // 2880 with padding

#define SIDX(i) ((i) + ((i) >> 3))

typedef unsigned long long u64;

__device__ __forceinline__ u64 pack2(float lo, float hi) {
    u64 r;
    asm("mov.b64 %0, {%1, %2};" : "=l"(r) : "f"(lo), "f"(hi));
    return r;
}

__device__ __forceinline__ u64 fma2(u64 a, u64 b, u64 c) {
    u64 d;
    asm("fma.rn.f32x2 %0, %1, %2, %3;" : "=l"(d) : "l"(a), "l"(b), "l"(c));
    return d;
}

__device__ __forceinline__ float2 unpack2(u64 v) {
    float lo, hi;
    asm("mov.b64 {%0, %1}, %2;" : "=f"(lo), "=f"(hi) : "l"(v));
    return make_float2(lo, hi);
}

__global__ void __launch_bounds__(THREADS, 3)
conv_dp_kernel(const float* __restrict__ txr, const float* __restrict__ txi,
               const float* __restrict__ hre, const float* __restrict__ him,
               float2* __restrict__ out, int N, int NOUT)
{
    __shared__ float2 sx[XPHYS];   // (xr, xi) zero-padded tile, bank-padded
    __shared__ float4 sh[NTAPS];   // (hr, hr, hi, hi) per tap

    const int pol = blockIdx.y;
    const int tileStart = blockIdx.x * TILE;
    const float* __restrict__ xr = txr + (size_t)pol * N;
    const float* __restrict__ xi = txi + (size_t)pol * N;

    for (int i = threadIdx.x; i < XTILE; i += THREADS) {
        int g = tileStart - HALO + i;
        float a = 0.0f, b = 0.0f;
        if ((unsigned)g < (unsigned)N) { a = xr[g]; b = xi[g]; }
        sx[SIDX(i)] = make_float2(a, b);
    }
    for (int k = threadIdx.x; k < NTAPS; k += THREADS) {
        float r = hre[k], m = him[k];
        sh[k] = make_float4(r, r, m, m);
    }
    __syncthreads();

    const int base = threadIdx.x * PT;

    u64 accA[PT], accB[PT];   // accA = sum hr*(xr,xi), accB = sum hi*(xr,xi)
    u64 w[16];                // circular window of packed (xr,xi)
#pragma unroll
    for (int j = 0; j < PT; j++) { accA[j] = pack2(0.0f, 0.0f); accB[j] = pack2(0.0f, 0.0f); }

    // Preload slots 0..7 = logical offsets 0..7 (tap k=512 positions).
#pragma unroll
    for (int u = 0; u < 8; u++) {
        float2 v = sx[SIDX(base + u)];
        w[u] = pack2(v.x, v.y);
    }

    // 64 chunks of 8 taps, processed as 32 double-chunks (ping-pong phases).
    // Logical offset l (from base) lives in slot l & 15. Window span per chunk
    // is 15 slots, so a 16-slot circular buffer with compile-time indices works.
#pragma unroll 1
    for (int cc = 0; cc < 32; cc++) {
        const int l0 = 16 * cc;

        // ---- phase 0: chunk start l0, slots of l0+d = d ----
#pragma unroll
        for (int u = 0; u < 8; u++) {
            float2 v = sx[SIDX(base + l0 + 8 + u)];
            w[8 + u] = pack2(v.x, v.y);
        }
#pragma unroll
        for (int t = 0; t < 8; t++) {
            float4 h4 = sh[512 - l0 - t];
            u64 hrr = pack2(h4.x, h4.y);
            u64 hii = pack2(h4.z, h4.w);
#pragma unroll
            for (int j = 0; j < PT; j++) {
                accA[j] = fma2(hrr, w[j + t], accA[j]);
                accB[j] = fma2(hii, w[j + t], accB[j]);
            }
        }

        // ---- phase 1: chunk start l0+8, slots of (l0+8)+d = (8+d)&15 ----
#pragma unroll
        for (int u = 0; u < 8; u++) {
            float2 v = sx[SIDX(base + l0 + 16 + u)];
            w[u] = pack2(v.x, v.y);
        }
#pragma unroll
        for (int t = 0; t < 8; t++) {
            float4 h4 = sh[512 - l0 - 8 - t];
            u64 hrr = pack2(h4.x, h4.y);
            u64 hii = pack2(h4.z, h4.w);
#pragma unroll
            for (int j = 0; j < PT; j++) {
                accA[j] = fma2(hrr, w[(8 + j + t) & 15], accA[j]);
                accB[j] = fma2(hii, w[(8 + j + t) & 15], accB[j]);
            }
        }
    }

    // Remainder tap k = 0 (logical offset 512 + j -> slot (512+j)&15 = j).
    {
        float4 h4 = sh[0];
        u64 hrr = pack2(h4.x, h4.y);
        u64 hii = pack2(h4.z, h4.w);
#pragma unroll
        for (int j = 0; j < PT; j++) {
            accA[j] = fma2(hrr, w[j], accA[j]);
            accB[j] = fma2(hii, w[j], accB[j]);
        }
    }

    // Combine: y_re = accA.lo - accB.hi, y_im = accA.hi + accB.lo.
    const int n0 = tileStart + base;
    if (n0 + PT <= NOUT) {
        float2* o = out + (size_t)pol * NOUT + n0;
#pragma unroll
        for (int j = 0; j < PT; j++) {
            float2 a = unpack2(accA[j]);
            float2 b = unpack2(accB[j]);
            o[j] = make_float2(a.x - b.y, a.y + b.x);
        }
    }
}

extern "C" void kernel_launch(void* const* d_in, const int* in_sizes, int n_in,
                              void* d_out, int out_size)
{
    const float* txr = (const float*)d_in[0];  // [2, N]
    const float* txi = (const float*)d_in[1];  // [2, N]
    const float* hre = (const float*)d_in[2];  // [L]
    const float* him = (const float*)d_in[3];  // [L]

    const int N    = in_sizes[0] / 2;
    const int L    = in_sizes[2];
    const int NOUT = N + L - 1;

    const int tiles = (NOUT + TILE - 1) / TILE;
    dim3 grid(tiles, 2);
    conv_dp_kernel<<<grid, THREADS>>>(txr, txi, hre, him, (float2*)d_out, N, NOUT);
}